// round 12
// baseline (speedup 1.0000x reference)
#include <cuda_runtime.h>
#include <cuda_bf16.h>
#include <cstdint>

#define TT 256
#define BB 128
#define II 512
#define HH 1024
#define GRID_P 128          // 4 batch-tiles x 32 j-tiles
#define XW 20               // xp kernel smem row stride (words)
#define RS2 268             // persistent smem row stride (words): conflict-free, 16B aligned

// persistent kernel smem word offsets
#define WC_A1 0
#define WC_A2 8576          // 32*268
#define WC_B1 17152
#define WC_B2 25728
#define WC_C0 34304         // fp32 Cbuf wk=0: 32x36
#define WC_C1 35456
#define WC_RED 36608
#define SMW   (36608 + 16)  // words -> 146496 bytes

// ---------------- scratch ---------------------------------------------------
__device__ float g_xp[(size_t)TT * BB * HH];
__device__ float g_hs[(size_t)TT * BB * HH];      // fp32 hidden history (for head)
__device__ unsigned g_h1w[2][BB * HH / 4];        // ping-pong h word1 (int8 x4)
__device__ unsigned g_h2w[2][BB * HH / 4];        // ping-pong h word2 (residual)
__device__ unsigned g_flags[GRID_P * 32];
__device__ unsigned g_gen;

// ---------------- bf16 split helpers (xp kernel) ----------------------------
__device__ __forceinline__ float bhi(float x) {
    unsigned u = __float_as_uint(x);
    u = (u + 0x7FFFu + ((u >> 16) & 1u)) & 0xFFFF0000u;
    return __uint_as_float(u);
}
__device__ __forceinline__ void split_pair(float e, float o, unsigned &whi, unsigned &wlo) {
    float eh = bhi(e), oh = bhi(o);
    whi = (__float_as_uint(eh) >> 16) | (__float_as_uint(oh) & 0xFFFF0000u);
    float el = e - eh, ol = o - oh;
    asm("cvt.rn.bf16x2.f32 %0, %1, %2;" : "=r"(wlo) : "f"(ol), "f"(el));
}

#define MMA_BF16(d, a, b)                                                       \
    asm volatile(                                                               \
        "mma.sync.aligned.m16n8k16.row.col.f32.bf16.bf16.f32 "                  \
        "{%0,%1,%2,%3},{%4,%5,%6,%7},{%8,%9},{%0,%1,%2,%3};\n"                  \
        : "+f"((d)[0]), "+f"((d)[1]), "+f"((d)[2]), "+f"((d)[3])                \
        : "r"((a)[0]), "r"((a)[1]), "r"((a)[2]), "r"((a)[3]),                   \
          "r"((b)[0]), "r"((b)[1]))

#define MMA_S8(d, a, b)                                                         \
    asm volatile(                                                               \
        "mma.sync.aligned.m16n8k32.row.col.s32.s8.s8.s32 "                      \
        "{%0,%1,%2,%3},{%4,%5,%6,%7},{%8,%9},{%0,%1,%2,%3};\n"                  \
        : "+r"((d)[0]), "+r"((d)[1]), "+r"((d)[2]), "+r"((d)[3])                \
        : "r"((a)[0]), "r"((a)[1]), "r"((a)[2]), "r"((a)[3]),                   \
          "r"((b)[0]), "r"((b)[1]))

__device__ __forceinline__ unsigned pack4(int a, int b, int c, int d) {
    return (unsigned)(a & 0xFF) | ((unsigned)(b & 0xFF) << 8) |
           ((unsigned)(c & 0xFF) << 16) | ((unsigned)(d & 0xFF) << 24);
}

// ---------------- flag barrier (single hop) ----------------------------------
__device__ __forceinline__ unsigned ld_acq(const unsigned* p) {
    unsigned v; asm volatile("ld.acquire.gpu.global.u32 %0, [%1];" : "=r"(v) : "l"(p)); return v;
}
__device__ __forceinline__ void st_rel(unsigned* p, unsigned v) {
    asm volatile("st.release.gpu.global.u32 [%0], %1;" :: "l"(p), "r"(v));
}
__device__ __forceinline__ void gsync(unsigned gen, int bxid, int tid) {
    __syncthreads();
    if (tid == 0) st_rel(&g_flags[bxid * 32], gen);
    if (tid < GRID_P) { while (ld_acq(&g_flags[tid * 32]) < gen) {} }
    __syncthreads();
}

// ---------------- init ------------------------------------------------------
__global__ void init_kernel() {
    int i = blockIdx.x * blockDim.x + threadIdx.x;
    if (i < BB * HH / 4) {
        g_h1w[0][i] = 0u; g_h2w[0][i] = 0u;
        g_h1w[1][i] = 0u; g_h2w[1][i] = 0u;
    }
    if (i < GRID_P * 32) g_flags[i] = 0u;
    if (i == 0) g_gen = 0u;
}

// ---------------------------------------------------------------------------
// xp = x @ W_ih^T + b_ih + b_hh via bf16x3 mma (unchanged).
// ---------------------------------------------------------------------------
__global__ __launch_bounds__(256) void xp_mma(const float* __restrict__ x,
                                              const float* __restrict__ Wih,
                                              const float* __restrict__ bih,
                                              const float* __restrict__ bhh) {
    __shared__ unsigned Ash[128 * XW], Asl[128 * XW];
    __shared__ unsigned Bsh[128 * XW], Bsl[128 * XW];

    int tid = threadIdx.x;
    int lane = tid & 31, w = tid >> 5;
    int g = lane >> 2, tg = lane & 3;
    int wm = (w & 1) * 64, wn = (w >> 1) * 32;
    int bn = blockIdx.x, bm = blockIdx.y;

    float acc[4][4][4];
    #pragma unroll
    for (int i = 0; i < 4; i++)
        #pragma unroll
        for (int j = 0; j < 4; j++)
            #pragma unroll
            for (int k = 0; k < 4; k++) acc[i][j][k] = 0.0f;

    int r = tid >> 1, half = tid & 1;
    const float* ax = x   + (size_t)(bm * 128 + r) * II + half * 16;
    const float* bw = Wih + (size_t)(bn * 128 + r) * II + half * 16;

    for (int kb = 0; kb < II; kb += 32) {
        unsigned hw[8], lw[8];
        #pragma unroll
        for (int i = 0; i < 4; i++) {
            float4 v = *(const float4*)(ax + kb + 4 * i);
            split_pair(v.x, v.y, hw[2 * i], lw[2 * i]);
            split_pair(v.z, v.w, hw[2 * i + 1], lw[2 * i + 1]);
        }
        {
            uint4* dh = (uint4*)&Ash[r * XW + half * 8];
            uint4* dl = (uint4*)&Asl[r * XW + half * 8];
            dh[0] = make_uint4(hw[0], hw[1], hw[2], hw[3]);
            dh[1] = make_uint4(hw[4], hw[5], hw[6], hw[7]);
            dl[0] = make_uint4(lw[0], lw[1], lw[2], lw[3]);
            dl[1] = make_uint4(lw[4], lw[5], lw[6], lw[7]);
        }
        #pragma unroll
        for (int i = 0; i < 4; i++) {
            float4 v = *(const float4*)(bw + kb + 4 * i);
            split_pair(v.x, v.y, hw[2 * i], lw[2 * i]);
            split_pair(v.z, v.w, hw[2 * i + 1], lw[2 * i + 1]);
        }
        {
            uint4* dh = (uint4*)&Bsh[r * XW + half * 8];
            uint4* dl = (uint4*)&Bsl[r * XW + half * 8];
            dh[0] = make_uint4(hw[0], hw[1], hw[2], hw[3]);
            dh[1] = make_uint4(hw[4], hw[5], hw[6], hw[7]);
            dl[0] = make_uint4(lw[0], lw[1], lw[2], lw[3]);
            dl[1] = make_uint4(lw[4], lw[5], lw[6], lw[7]);
        }
        __syncthreads();

        #pragma unroll
        for (int ki = 0; ki < 2; ki++) {
            int k0 = ki * 8;
            unsigned ah[4][4], al[4][4], bh[4][2], bl[4][2];
            #pragma unroll
            for (int mi = 0; mi < 4; mi++) {
                int base = (wm + 16 * mi + g) * XW + k0 + tg;
                ah[mi][0] = Ash[base];          ah[mi][1] = Ash[base + 8 * XW];
                ah[mi][2] = Ash[base + 4];      ah[mi][3] = Ash[base + 8 * XW + 4];
                al[mi][0] = Asl[base];          al[mi][1] = Asl[base + 8 * XW];
                al[mi][2] = Asl[base + 4];      al[mi][3] = Asl[base + 8 * XW + 4];
            }
            #pragma unroll
            for (int ni = 0; ni < 4; ni++) {
                int base = (wn + 8 * ni + g) * XW + k0 + tg;
                bh[ni][0] = Bsh[base]; bh[ni][1] = Bsh[base + 4];
                bl[ni][0] = Bsl[base]; bl[ni][1] = Bsl[base + 4];
            }
            #pragma unroll
            for (int mi = 0; mi < 4; mi++)
                #pragma unroll
                for (int ni = 0; ni < 4; ni++) {
                    MMA_BF16(acc[mi][ni], ah[mi], bh[ni]);
                    MMA_BF16(acc[mi][ni], ah[mi], bl[ni]);
                    MMA_BF16(acc[mi][ni], al[mi], bh[ni]);
                }
        }
        __syncthreads();
    }

    #pragma unroll
    for (int mi = 0; mi < 4; mi++)
        #pragma unroll
        for (int ni = 0; ni < 4; ni++) {
            int m = bm * 128 + wm + 16 * mi + g;
            int n = bn * 128 + wn + 8 * ni + 2 * tg;
            float b0 = bih[n] + bhh[n];
            float b1 = bih[n + 1] + bhh[n + 1];
            *(float2*)(g_xp + (size_t)m * HH + n) =
                make_float2(acc[mi][ni][0] + b0, acc[mi][ni][1] + b1);
            *(float2*)(g_xp + (size_t)(m + 8) * HH + n) =
                make_float2(acc[mi][ni][2] + b0, acc[mi][ni][3] + b1);
        }
}

// ---------------------------------------------------------------------------
// Persistent recurrence, single-phase: 128 CTAs = 4 bt x 32 jt, 256 threads.
// CTA computes full-K 32x32 tile, tanh, quantizes h. ONE gsync per step.
// ---------------------------------------------------------------------------
__global__ __launch_bounds__(256, 1) void rnn_persistent(const float* __restrict__ Whh,
                                                         float* __restrict__ out) {
    extern __shared__ unsigned smw[];
    unsigned* A1 = smw + WC_A1;
    unsigned* A2 = smw + WC_A2;
    unsigned* B1 = smw + WC_B1;
    unsigned* B2 = smw + WC_B2;
    float* C0 = (float*)(smw + WC_C0);
    float* C1s = (float*)(smw + WC_C1);
    float* redf = (float*)(smw + WC_RED);

    int tid = threadIdx.x;
    int bxid = blockIdx.x;
    int bt = bxid >> 5;          // batch tile 0..3
    int jt = bxid & 31;          // j tile 0..31
    int lane = tid & 31, w = tid >> 5;
    int g = lane >> 2, tg = lane & 3;
    int wk = w >> 2;                       // K half
    int wm = (w & 1) * 16;                 // warp m offset
    int wn = ((w >> 1) & 1) * 16;          // warp n offset

    // ---- prologue: split W_hh rows jt*32..+31 (full K) to int8 dual-word ----
    float c1, c2;
    {
        int n = tid >> 3;            // 0..31 local row
        int seg = tid & 7;           // 128-k segment
        const float* src = Whh + (size_t)(jt * 32 + n) * HH + seg * 128;

        float m = 0.0f;
        #pragma unroll
        for (int i = 0; i < 32; i++) {
            float4 v = ((const float4*)src)[i];
            m = fmaxf(m, fmaxf(fmaxf(fabsf(v.x), fabsf(v.y)),
                               fmaxf(fabsf(v.z), fabsf(v.w))));
        }
        #pragma unroll
        for (int o = 16; o > 0; o >>= 1)
            m = fmaxf(m, __shfl_xor_sync(0xFFFFFFFFu, m, o));
        if (lane == 0) redf[w] = m;
        __syncthreads();
        if (tid == 0) {
            float mm = redf[0];
            #pragma unroll
            for (int i = 1; i < 8; i++) mm = fmaxf(mm, redf[i]);
            redf[8] = mm;
        }
        __syncthreads();
        float Sw = 127.0f / redf[8];
        c1 = 1.0f / (Sw * 127.0f);
        c2 = c1 * (1.0f / 254.0f);

        #pragma unroll
        for (int qi = 0; qi < 8; qi++) {
            unsigned w1[4], w2[4];
            #pragma unroll
            for (int f = 0; f < 4; f++) {
                float4 v = ((const float4*)src)[qi * 4 + f];
                float fv[4] = {v.x, v.y, v.z, v.w};
                int i1[4], i2[4];
                #pragma unroll
                for (int e = 0; e < 4; e++) {
                    float s = fv[e] * Sw;
                    i1[e] = (int)rintf(s);
                    i2[e] = (int)rintf((s - (float)i1[e]) * 254.0f);
                }
                w1[f] = pack4(i1[0], i1[1], i1[2], i1[3]);
                w2[f] = pack4(i2[0], i2[1], i2[2], i2[3]);
            }
            *(uint4*)&B1[n * RS2 + seg * 32 + qi * 4] = make_uint4(w1[0], w1[1], w1[2], w1[3]);
            *(uint4*)&B2[n * RS2 + seg * 32 + qi * 4] = make_uint4(w2[0], w2[1], w2[2], w2[3]);
        }
    }
    __syncthreads();

    unsigned gen = 0;

    for (int t = 0; t < TT; t++) {
        int p = t & 1;           // read buffer
        int pw = p ^ 1;          // write buffer

        // ---- stage h slice: batches bt*32..+31, all 1024 k (packed int8) ----
        {
            int r = tid >> 3, seg = tid & 7;
            const uint4* s1 = (const uint4*)&g_h1w[p][(bt * 32 + r) * 256 + seg * 32];
            const uint4* s2 = (const uint4*)&g_h2w[p][(bt * 32 + r) * 256 + seg * 32];
            uint4* d1 = (uint4*)&A1[r * RS2 + seg * 32];
            uint4* d2 = (uint4*)&A2[r * RS2 + seg * 32];
            #pragma unroll
            for (int i = 0; i < 8; i++) { d1[i] = s1[i]; d2[i] = s2[i]; }
        }
        __syncthreads();

        // ---- full-K MMA: warp handles 16x16 tile, K half wk ----
        int acc1[2][4], acc2[2][4];
        #pragma unroll
        for (int ni = 0; ni < 2; ni++)
            #pragma unroll
            for (int k = 0; k < 4; k++) { acc1[ni][k] = 0; acc2[ni][k] = 0; }

        #pragma unroll
        for (int c = 0; c < 16; c++) {
            int kc = wk * 16 + c;
            int ab = (wm + g) * RS2 + kc * 8 + tg;
            int ab8 = ab + 8 * RS2;
            unsigned a1[4], a2[4];
            a1[0] = A1[ab];     a1[1] = A1[ab8];
            a1[2] = A1[ab + 4]; a1[3] = A1[ab8 + 4];
            a2[0] = A2[ab];     a2[1] = A2[ab8];
            a2[2] = A2[ab + 4]; a2[3] = A2[ab8 + 4];
            #pragma unroll
            for (int ni = 0; ni < 2; ni++) {
                int bb = (wn + 8 * ni + g) * RS2 + kc * 8 + tg;
                unsigned b1[2], b2[2];
                b1[0] = B1[bb]; b1[1] = B1[bb + 4];
                b2[0] = B2[bb]; b2[1] = B2[bb + 4];
                MMA_S8(acc1[ni], a1, b1);
                MMA_S8(acc2[ni], a1, b2);
                MMA_S8(acc2[ni], a2, b1);
            }
        }

        // ---- combine into fp32 Cbuf (per K-half) ----
        {
            float* Cb = wk ? C1s : C0;
            #pragma unroll
            for (int ni = 0; ni < 2; ni++) {
                int colb = wn + 8 * ni + 2 * tg;
                float v0 = c1 * (float)acc1[ni][0] + c2 * (float)acc2[ni][0];
                float v1 = c1 * (float)acc1[ni][1] + c2 * (float)acc2[ni][1];
                float v2 = c1 * (float)acc1[ni][2] + c2 * (float)acc2[ni][2];
                float v3 = c1 * (float)acc1[ni][3] + c2 * (float)acc2[ni][3];
                *(float2*)&Cb[(wm + g) * 36 + colb] = make_float2(v0, v1);
                *(float2*)&Cb[(wm + g + 8) * 36 + colb] = make_float2(v2, v3);
            }
        }
        __syncthreads();

        // ---- pack: add K halves + xp, tanh, store h (fp32 hist + int8 x2) ----
        {
            int rr = tid >> 3, c8 = tid & 7;
            int b = bt * 32 + rr;
            int j = jt * 32 + c8 * 4;
            float4 s0 = *(float4*)&C0[rr * 36 + c8 * 4];
            float4 s1 = *(float4*)&C1s[rr * 36 + c8 * 4];
            float4 xv = *(const float4*)(g_xp + ((size_t)t * BB + b) * HH + j);
            float h0 = tanhf(s0.x + s1.x + xv.x);
            float h1 = tanhf(s0.y + s1.y + xv.y);
            float h2 = tanhf(s0.z + s1.z + xv.z);
            float h3 = tanhf(s0.w + s1.w + xv.w);

            *(float4*)(g_hs + ((size_t)t * BB + b) * HH + j) =
                make_float4(h0, h1, h2, h3);

            float hv[4] = {h0, h1, h2, h3};
            int i1[4], i2[4];
            #pragma unroll
            for (int e = 0; e < 4; e++) {
                float sc = hv[e] * 127.0f;
                i1[e] = (int)rintf(sc);
                i2[e] = (int)rintf((sc - (float)i1[e]) * 254.0f);
            }
            g_h1w[pw][b * 256 + jt * 8 + c8] = pack4(i1[0], i1[1], i1[2], i1[3]);
            g_h2w[pw][b * 256 + jt * 8 + c8] = pack4(i2[0], i2[1], i2[2], i2[3]);
        }
        gsync(++gen, bxid, tid);
    }
}

// ---------------------------------------------------------------------------
// Head: out[t,b] = hs[t,b,:] . Wfc + bfc. One warp per (t,b), Wfc in smem.
// ---------------------------------------------------------------------------
__global__ __launch_bounds__(256) void head_kernel(const float* __restrict__ Wfc,
                                                   const float* __restrict__ bfc,
                                                   float* __restrict__ out) {
    __shared__ float wfs[HH];
    int tid = threadIdx.x;
    *(float4*)&wfs[tid * 4] = *(const float4*)(Wfc + tid * 4);
    __syncthreads();

    int lane = tid & 31, w = tid >> 5;
    int gw = blockIdx.x * 8 + w;           // 0..32767
    int t = gw >> 7, b = gw & 127;

    const float* hrow = g_hs + ((size_t)t * BB + b) * HH;
    float dot = 0.0f;
    #pragma unroll
    for (int i = 0; i < 8; i++) {
        int j = i * 128 + lane * 4;
        float4 h = *(const float4*)(hrow + j);
        float4 wv = *(const float4*)&wfs[j];
        dot += h.x * wv.x + h.y * wv.y + h.z * wv.z + h.w * wv.w;
    }
    #pragma unroll
    for (int o = 16; o > 0; o >>= 1)
        dot += __shfl_down_sync(0xFFFFFFFFu, dot, o);
    if (lane == 0) out[t * BB + b] = dot + bfc[0];
}

// ---------------------------------------------------------------------------
extern "C" void kernel_launch(void* const* d_in, const int* in_sizes, int n_in,
                              void* d_out, int out_size) {
    const float* x   = (const float*)d_in[0];
    const float* Wih = (const float*)d_in[1];
    const float* Whh = (const float*)d_in[2];
    const float* bih = (const float*)d_in[3];
    const float* bhh = (const float*)d_in[4];
    const float* Wfc = (const float*)d_in[5];
    const float* bfc = (const float*)d_in[6];
    float* out = (float*)d_out;

    static int configured = 0;
    if (!configured) {
        cudaFuncSetAttribute(rnn_persistent, cudaFuncAttributeMaxDynamicSharedMemorySize,
                             SMW * 4);
        configured = 1;
    }

    init_kernel<<<512, 256>>>();
    xp_mma<<<dim3(8, 256), 256>>>(x, Wih, bih, bhh);
    rnn_persistent<<<GRID_P, 256, SMW * 4>>>(Whh, out);
    head_kernel<<<4096, 256>>>(Wfc, bfc, out);
}

// round 14
// speedup vs baseline: 1.3220x; 1.3220x over previous
#include <cuda_runtime.h>
#include <cuda_bf16.h>
#include <cstdint>

#define TT 256
#define BB 128
#define II 512
#define HH 1024
#define GRID_P 128          // 4 batch-tiles x 32 j-tiles
#define XW 20               // xp kernel smem row stride (words)
#define RS3 260             // A/B row stride words: 256 data + 4 pad (== 4 mod 32)

// persistent kernel smem word offsets
#define WC_A1 0
#define WC_A2 8320          // 32*260
#define WC_B1 16640
#define WC_B2 24960
#define WC_C  33280         // 8 bufs x 32x36 fp32
#define WC_RED 42496
#define SMW3  (42496 + 16)  // words -> 170048 bytes

// ---------------- scratch ---------------------------------------------------
__device__ float g_xp[(size_t)TT * BB * HH];
__device__ float g_hs[(size_t)TT * BB * HH];      // fp32 hidden history (head)
__device__ unsigned g_h1w[2][BB * HH / 4];        // ping-pong h word1 (int8 x4)
__device__ unsigned g_h2w[2][BB * HH / 4];        // ping-pong h word2 (residual)
__device__ unsigned g_flags[GRID_P * 32];
__device__ unsigned g_gen;

// ---------------- bf16 split helpers (xp kernel) ----------------------------
__device__ __forceinline__ float bhi(float x) {
    unsigned u = __float_as_uint(x);
    u = (u + 0x7FFFu + ((u >> 16) & 1u)) & 0xFFFF0000u;
    return __uint_as_float(u);
}
__device__ __forceinline__ void split_pair(float e, float o, unsigned &whi, unsigned &wlo) {
    float eh = bhi(e), oh = bhi(o);
    whi = (__float_as_uint(eh) >> 16) | (__float_as_uint(oh) & 0xFFFF0000u);
    float el = e - eh, ol = o - oh;
    asm("cvt.rn.bf16x2.f32 %0, %1, %2;" : "=r"(wlo) : "f"(ol), "f"(el));
}

#define MMA_BF16(d, a, b)                                                       \
    asm volatile(                                                               \
        "mma.sync.aligned.m16n8k16.row.col.f32.bf16.bf16.f32 "                  \
        "{%0,%1,%2,%3},{%4,%5,%6,%7},{%8,%9},{%0,%1,%2,%3};\n"                  \
        : "+f"((d)[0]), "+f"((d)[1]), "+f"((d)[2]), "+f"((d)[3])                \
        : "r"((a)[0]), "r"((a)[1]), "r"((a)[2]), "r"((a)[3]),                   \
          "r"((b)[0]), "r"((b)[1]))

#define MMA_S8(d, a, b)                                                         \
    asm volatile(                                                               \
        "mma.sync.aligned.m16n8k32.row.col.s32.s8.s8.s32 "                      \
        "{%0,%1,%2,%3},{%4,%5,%6,%7},{%8,%9},{%0,%1,%2,%3};\n"                  \
        : "+r"((d)[0]), "+r"((d)[1]), "+r"((d)[2]), "+r"((d)[3])                \
        : "r"((a)[0]), "r"((a)[1]), "r"((a)[2]), "r"((a)[3]),                   \
          "r"((b)[0]), "r"((b)[1]))

__device__ __forceinline__ unsigned pack4(int a, int b, int c, int d) {
    return (unsigned)(a & 0xFF) | ((unsigned)(b & 0xFF) << 8) |
           ((unsigned)(c & 0xFF) << 16) | ((unsigned)(d & 0xFF) << 24);
}

// ---------------- flag barrier (single hop) ----------------------------------
__device__ __forceinline__ unsigned ld_acq(const unsigned* p) {
    unsigned v; asm volatile("ld.acquire.gpu.global.u32 %0, [%1];" : "=r"(v) : "l"(p)); return v;
}
__device__ __forceinline__ void st_rel(unsigned* p, unsigned v) {
    asm volatile("st.release.gpu.global.u32 [%0], %1;" :: "l"(p), "r"(v));
}
__device__ __forceinline__ void gsync(unsigned gen, int bxid, int tid) {
    __syncthreads();
    if (tid == 0) st_rel(&g_flags[bxid * 32], gen);
    if (tid < GRID_P) { while (ld_acq(&g_flags[tid * 32]) < gen) {} }
    __syncthreads();
}

// ---------------- init ------------------------------------------------------
__global__ void init_kernel() {
    int i = blockIdx.x * blockDim.x + threadIdx.x;
    if (i < BB * HH / 4) {
        g_h1w[0][i] = 0u; g_h2w[0][i] = 0u;
        g_h1w[1][i] = 0u; g_h2w[1][i] = 0u;
    }
    if (i < GRID_P * 32) g_flags[i] = 0u;
    if (i == 0) g_gen = 0u;
}

// ---------------------------------------------------------------------------
// xp = x @ W_ih^T + b_ih + b_hh via bf16x3 mma (unchanged).
// ---------------------------------------------------------------------------
__global__ __launch_bounds__(256) void xp_mma(const float* __restrict__ x,
                                              const float* __restrict__ Wih,
                                              const float* __restrict__ bih,
                                              const float* __restrict__ bhh) {
    __shared__ unsigned Ash[128 * XW], Asl[128 * XW];
    __shared__ unsigned Bsh[128 * XW], Bsl[128 * XW];

    int tid = threadIdx.x;
    int lane = tid & 31, w = tid >> 5;
    int g = lane >> 2, tg = lane & 3;
    int wm = (w & 1) * 64, wn = (w >> 1) * 32;
    int bn = blockIdx.x, bm = blockIdx.y;

    float acc[4][4][4];
    #pragma unroll
    for (int i = 0; i < 4; i++)
        #pragma unroll
        for (int j = 0; j < 4; j++)
            #pragma unroll
            for (int k = 0; k < 4; k++) acc[i][j][k] = 0.0f;

    int r = tid >> 1, half = tid & 1;
    const float* ax = x   + (size_t)(bm * 128 + r) * II + half * 16;
    const float* bw = Wih + (size_t)(bn * 128 + r) * II + half * 16;

    for (int kb = 0; kb < II; kb += 32) {
        unsigned hw[8], lw[8];
        #pragma unroll
        for (int i = 0; i < 4; i++) {
            float4 v = *(const float4*)(ax + kb + 4 * i);
            split_pair(v.x, v.y, hw[2 * i], lw[2 * i]);
            split_pair(v.z, v.w, hw[2 * i + 1], lw[2 * i + 1]);
        }
        {
            uint4* dh = (uint4*)&Ash[r * XW + half * 8];
            uint4* dl = (uint4*)&Asl[r * XW + half * 8];
            dh[0] = make_uint4(hw[0], hw[1], hw[2], hw[3]);
            dh[1] = make_uint4(hw[4], hw[5], hw[6], hw[7]);
            dl[0] = make_uint4(lw[0], lw[1], lw[2], lw[3]);
            dl[1] = make_uint4(lw[4], lw[5], lw[6], lw[7]);
        }
        #pragma unroll
        for (int i = 0; i < 4; i++) {
            float4 v = *(const float4*)(bw + kb + 4 * i);
            split_pair(v.x, v.y, hw[2 * i], lw[2 * i]);
            split_pair(v.z, v.w, hw[2 * i + 1], lw[2 * i + 1]);
        }
        {
            uint4* dh = (uint4*)&Bsh[r * XW + half * 8];
            uint4* dl = (uint4*)&Bsl[r * XW + half * 8];
            dh[0] = make_uint4(hw[0], hw[1], hw[2], hw[3]);
            dh[1] = make_uint4(hw[4], hw[5], hw[6], hw[7]);
            dl[0] = make_uint4(lw[0], lw[1], lw[2], lw[3]);
            dl[1] = make_uint4(lw[4], lw[5], lw[6], lw[7]);
        }
        __syncthreads();

        #pragma unroll
        for (int ki = 0; ki < 2; ki++) {
            int k0 = ki * 8;
            unsigned ah[4][4], al[4][4], bh[4][2], bl[4][2];
            #pragma unroll
            for (int mi = 0; mi < 4; mi++) {
                int base = (wm + 16 * mi + g) * XW + k0 + tg;
                ah[mi][0] = Ash[base];          ah[mi][1] = Ash[base + 8 * XW];
                ah[mi][2] = Ash[base + 4];      ah[mi][3] = Ash[base + 8 * XW + 4];
                al[mi][0] = Asl[base];          al[mi][1] = Asl[base + 8 * XW];
                al[mi][2] = Asl[base + 4];      al[mi][3] = Asl[base + 8 * XW + 4];
            }
            #pragma unroll
            for (int ni = 0; ni < 4; ni++) {
                int base = (wn + 8 * ni + g) * XW + k0 + tg;
                bh[ni][0] = Bsh[base]; bh[ni][1] = Bsh[base + 4];
                bl[ni][0] = Bsl[base]; bl[ni][1] = Bsl[base + 4];
            }
            #pragma unroll
            for (int mi = 0; mi < 4; mi++)
                #pragma unroll
                for (int ni = 0; ni < 4; ni++) {
                    MMA_BF16(acc[mi][ni], ah[mi], bh[ni]);
                    MMA_BF16(acc[mi][ni], ah[mi], bl[ni]);
                    MMA_BF16(acc[mi][ni], al[mi], bh[ni]);
                }
        }
        __syncthreads();
    }

    #pragma unroll
    for (int mi = 0; mi < 4; mi++)
        #pragma unroll
        for (int ni = 0; ni < 4; ni++) {
            int m = bm * 128 + wm + 16 * mi + g;
            int n = bn * 128 + wn + 8 * ni + 2 * tg;
            float b0 = bih[n] + bhh[n];
            float b1 = bih[n + 1] + bhh[n + 1];
            *(float2*)(g_xp + (size_t)m * HH + n) =
                make_float2(acc[mi][ni][0] + b0, acc[mi][ni][1] + b1);
            *(float2*)(g_xp + (size_t)(m + 8) * HH + n) =
                make_float2(acc[mi][ni][2] + b0, acc[mi][ni][3] + b1);
        }
}

// ---------------------------------------------------------------------------
// Persistent recurrence: 128 CTAs = 4 bt x 32 jt; warps split K (each warp
// m32 x n32 x k128 - R10 fragment economics); one grid sync per step.
// ---------------------------------------------------------------------------
__global__ __launch_bounds__(256, 1) void rnn_persistent(const float* __restrict__ Whh,
                                                         float* __restrict__ out) {
    extern __shared__ unsigned smw[];
    unsigned* A1 = smw + WC_A1;
    unsigned* A2 = smw + WC_A2;
    unsigned* B1 = smw + WC_B1;
    unsigned* B2 = smw + WC_B2;
    float* Cb = (float*)(smw + WC_C);      // 8 bufs of 32x36
    float* redf = (float*)(smw + WC_RED);

    int tid = threadIdx.x;
    int bxid = blockIdx.x;
    int bt = bxid >> 5;          // batch tile 0..3
    int jt = bxid & 31;          // j tile 0..31
    int lane = tid & 31, w = tid >> 5;
    int g = lane >> 2, tg = lane & 3;

    // ---- prologue: W_hh rows jt*32..+31, full K -> int8 dual-word smem -----
    float c1, c2;
    {
        int n = tid >> 3;            // local j row 0..31
        int seg = tid & 7;           // 128-float k segment
        const float* src = Whh + (size_t)(jt * 32 + n) * HH + seg * 128;

        float m = 0.0f;
        #pragma unroll
        for (int i = 0; i < 32; i++) {
            float4 v = ((const float4*)src)[i];
            m = fmaxf(m, fmaxf(fmaxf(fabsf(v.x), fabsf(v.y)),
                               fmaxf(fabsf(v.z), fabsf(v.w))));
        }
        #pragma unroll
        for (int o = 16; o > 0; o >>= 1)
            m = fmaxf(m, __shfl_xor_sync(0xFFFFFFFFu, m, o));
        if (lane == 0) redf[w] = m;
        __syncthreads();
        if (tid == 0) {
            float mm = redf[0];
            #pragma unroll
            for (int i = 1; i < 8; i++) mm = fmaxf(mm, redf[i]);
            redf[8] = mm;
        }
        __syncthreads();
        float Sw = 127.0f / redf[8];
        c1 = 1.0f / (Sw * 127.0f);
        c2 = c1 * (1.0f / 254.0f);

        #pragma unroll
        for (int qi = 0; qi < 8; qi++) {
            unsigned w1[4], w2[4];
            #pragma unroll
            for (int f = 0; f < 4; f++) {
                float4 v = ((const float4*)src)[qi * 4 + f];
                float fv[4] = {v.x, v.y, v.z, v.w};
                int i1[4], i2[4];
                #pragma unroll
                for (int e = 0; e < 4; e++) {
                    float s = fv[e] * Sw;
                    i1[e] = (int)rintf(s);
                    i2[e] = (int)rintf((s - (float)i1[e]) * 254.0f);
                }
                w1[f] = pack4(i1[0], i1[1], i1[2], i1[3]);
                w2[f] = pack4(i2[0], i2[1], i2[2], i2[3]);
            }
            *(uint4*)&B1[n * RS3 + seg * 32 + qi * 4] = make_uint4(w1[0], w1[1], w1[2], w1[3]);
            *(uint4*)&B2[n * RS3 + seg * 32 + qi * 4] = make_uint4(w2[0], w2[1], w2[2], w2[3]);
        }
    }
    __syncthreads();

    // staging lane map (conflict-free STS.128): 4 rows/warp, rotated k position
    int srow = w * 4 + (lane >> 3);                 // 0..31
    int sq   = ((lane & 7) + (lane >> 3)) & 7;      // rotated 16B slot
    // pack-phase role
    int rr = tid >> 3, c8 = tid & 7;                // 32 rows x 8 word-cols
    int bglob = bt * 32 + rr;

    unsigned gen = 0;

    for (int t = 0; t < TT; t++) {
        int p = t & 1, pw = p ^ 1;

        // prefetch xp for this thread's pack element (independent of h)
        float4 xv = *(const float4*)(g_xp + ((size_t)t * BB + bglob) * HH + jt * 32 + c8 * 4);

        // ---- stage h: 32 batches x 1024 k, packed int8 dual-word ----
        {
            const unsigned* s1 = &g_h1w[p][(bt * 32 + srow) * 256];
            const unsigned* s2 = &g_h2w[p][(bt * 32 + srow) * 256];
            unsigned* d1 = &A1[srow * RS3];
            unsigned* d2 = &A2[srow * RS3];
            #pragma unroll
            for (int ch = 0; ch < 8; ch++) {
                int o = ch * 32 + sq * 4;
                uint4 v1 = *(const uint4*)(s1 + o);
                uint4 v2 = *(const uint4*)(s2 + o);
                *(uint4*)(d1 + o) = v1;
                *(uint4*)(d2 + o) = v2;
            }
        }
        __syncthreads();

        // ---- MMA: warp w covers k words w*32..+31 (k bytes w*128..+128) ----
        int acc1[2][4][4], acc2[2][4][4];
        #pragma unroll
        for (int i = 0; i < 2; i++)
            #pragma unroll
            for (int j = 0; j < 4; j++)
                #pragma unroll
                for (int k = 0; k < 4; k++) { acc1[i][j][k] = 0; acc2[i][j][k] = 0; }

        #pragma unroll
        for (int c = 0; c < 4; c++) {
            int kw = w * 32 + c * 8 + tg;
            unsigned a1[2][4], a2[2][4], b1[4][2], b2[4][2];
            #pragma unroll
            for (int mi = 0; mi < 2; mi++) {
                int ab = (16 * mi + g) * RS3 + kw;
                int ab8 = ab + 8 * RS3;
                a1[mi][0] = A1[ab];     a1[mi][1] = A1[ab8];
                a1[mi][2] = A1[ab + 4]; a1[mi][3] = A1[ab8 + 4];
                a2[mi][0] = A2[ab];     a2[mi][1] = A2[ab8];
                a2[mi][2] = A2[ab + 4]; a2[mi][3] = A2[ab8 + 4];
            }
            #pragma unroll
            for (int ni = 0; ni < 4; ni++) {
                int bb = (8 * ni + g) * RS3 + kw;
                b1[ni][0] = B1[bb]; b1[ni][1] = B1[bb + 4];
                b2[ni][0] = B2[bb]; b2[ni][1] = B2[bb + 4];
            }
            #pragma unroll
            for (int mi = 0; mi < 2; mi++)
                #pragma unroll
                for (int ni = 0; ni < 4; ni++) {
                    MMA_S8(acc1[mi][ni], a1[mi], b1[ni]);
                    MMA_S8(acc2[mi][ni], a1[mi], b2[ni]);
                    MMA_S8(acc2[mi][ni], a2[mi], b1[ni]);
                }
        }

        // ---- epilogue: scale to fp32, write per-warp C buffer ----
        {
            float* Cw = Cb + w * (32 * 36);
            #pragma unroll
            for (int mi = 0; mi < 2; mi++)
                #pragma unroll
                for (int ni = 0; ni < 4; ni++) {
                    int row = 16 * mi + g;
                    int col = 8 * ni + 2 * tg;
                    float v0 = c1 * (float)acc1[mi][ni][0] + c2 * (float)acc2[mi][ni][0];
                    float v1 = c1 * (float)acc1[mi][ni][1] + c2 * (float)acc2[mi][ni][1];
                    float v2 = c1 * (float)acc1[mi][ni][2] + c2 * (float)acc2[mi][ni][2];
                    float v3 = c1 * (float)acc1[mi][ni][3] + c2 * (float)acc2[mi][ni][3];
                    *(float2*)&Cw[row * 36 + col] = make_float2(v0, v1);
                    *(float2*)&Cw[(row + 8) * 36 + col] = make_float2(v2, v3);
                }
        }
        __syncthreads();

        // ---- reduce 8 K-chunks + xp, tanh, store h (fp32 hist + int8 x2) ----
        {
            float4 s = xv;
            #pragma unroll
            for (int buf = 0; buf < 8; buf++) {
                float4 v = *(float4*)&Cb[buf * (32 * 36) + rr * 36 + c8 * 4];
                s.x += v.x; s.y += v.y; s.z += v.z; s.w += v.w;
            }
            float h0 = tanhf(s.x), h1 = tanhf(s.y), h2 = tanhf(s.z), h3 = tanhf(s.w);

            *(float4*)(g_hs + ((size_t)t * BB + bglob) * HH + jt * 32 + c8 * 4) =
                make_float4(h0, h1, h2, h3);

            float hv[4] = {h0, h1, h2, h3};
            int i1[4], i2[4];
            #pragma unroll
            for (int e = 0; e < 4; e++) {
                float sc = hv[e] * 127.0f;
                i1[e] = (int)rintf(sc);
                i2[e] = (int)rintf((sc - (float)i1[e]) * 254.0f);
            }
            g_h1w[pw][bglob * 256 + jt * 8 + c8] = pack4(i1[0], i1[1], i1[2], i1[3]);
            g_h2w[pw][bglob * 256 + jt * 8 + c8] = pack4(i2[0], i2[1], i2[2], i2[3]);
        }
        gsync(++gen, bxid, tid);
    }
}

// ---------------------------------------------------------------------------
// Head: out[t,b] = hs[t,b,:] . Wfc + bfc. One warp per (t,b), Wfc in smem.
// ---------------------------------------------------------------------------
__global__ __launch_bounds__(256) void head_kernel(const float* __restrict__ Wfc,
                                                   const float* __restrict__ bfc,
                                                   float* __restrict__ out) {
    __shared__ float wfs[HH];
    int tid = threadIdx.x;
    *(float4*)&wfs[tid * 4] = *(const float4*)(Wfc + tid * 4);
    __syncthreads();

    int lane = tid & 31, w = tid >> 5;
    int gw = blockIdx.x * 8 + w;           // 0..32767
    int t = gw >> 7, b = gw & 127;

    const float* hrow = g_hs + ((size_t)t * BB + b) * HH;
    float dot = 0.0f;
    #pragma unroll
    for (int i = 0; i < 8; i++) {
        int j = i * 128 + lane * 4;
        float4 h = *(const float4*)(hrow + j);
        float4 wv = *(const float4*)&wfs[j];
        dot += h.x * wv.x + h.y * wv.y + h.z * wv.z + h.w * wv.w;
    }
    #pragma unroll
    for (int o = 16; o > 0; o >>= 1)
        dot += __shfl_down_sync(0xFFFFFFFFu, dot, o);
    if (lane == 0) out[t * BB + b] = dot + bfc[0];
}

// ---------------------------------------------------------------------------
extern "C" void kernel_launch(void* const* d_in, const int* in_sizes, int n_in,
                              void* d_out, int out_size) {
    const float* x   = (const float*)d_in[0];
    const float* Wih = (const float*)d_in[1];
    const float* Whh = (const float*)d_in[2];
    const float* bih = (const float*)d_in[3];
    const float* bhh = (const float*)d_in[4];
    const float* Wfc = (const float*)d_in[5];
    const float* bfc = (const float*)d_in[6];
    float* out = (float*)d_out;

    static int configured = 0;
    if (!configured) {
        cudaFuncSetAttribute(rnn_persistent, cudaFuncAttributeMaxDynamicSharedMemorySize,
                             SMW3 * 4);
        configured = 1;
    }

    init_kernel<<<512, 256>>>();
    xp_mma<<<dim3(8, 256), 256>>>(x, Wih, bih, bhh);
    rnn_persistent<<<GRID_P, 256, SMW3 * 4>>>(Whh, out);
    head_kernel<<<4096, 256>>>(Wfc, bfc, out);
}